// round 3
// baseline (speedup 1.0000x reference)
#include <cuda_runtime.h>

#define B_  128
#define T_  128
#define H_  1024
#define L_  2
#define N3_ 3072          // 3*H
#define M_  16384         // B*T

// ---------------- device scratch (static globals; no allocation) ----------------
__device__ float g_xp[(size_t)M_ * N3_];      // 201 MB: xp for current layer, [B*T, 3H], row m=(b,t)
__device__ float g_seq1[(size_t)M_ * H_];     // 64 MB: layer-1 output sequence, [B*T, H]
__device__ float g_hbuf[2][B_ * H_];          // ping-pong hidden state

// ---------------- big GEMM: C[m,n] = sum_k A[m,k]*W[n,k] + bias[n] ----------------
// 128x128 tile, k-chunk 8, 256 threads, 8x8 micro-tile. M,N %128==0, K %8==0 assumed.
__global__ __launch_bounds__(256) void sgemm_nt_bias(
    const float* __restrict__ A, const float* __restrict__ W,
    const float* __restrict__ bias, float* __restrict__ C,
    int M, int N, int K)
{
    __shared__ __align__(16) float As[8][128];
    __shared__ __align__(16) float Bs[8][128];
    const int tid = threadIdx.x;
    const int m0 = blockIdx.y * 128;
    const int n0 = blockIdx.x * 128;

    // loaders: 2 threads per row, each one float4 along k
    const int lr = tid >> 1;
    const int lk = (tid & 1) << 2;
    const float* Ap = A + (size_t)(m0 + lr) * K + lk;
    const float* Wp = W + (size_t)(n0 + lr) * K + lk;

    const int tx = tid & 15;   // 8 output cols
    const int ty = tid >> 4;   // 8 output rows

    float acc[8][8];
#pragma unroll
    for (int i = 0; i < 8; i++)
#pragma unroll
        for (int j = 0; j < 8; j++) acc[i][j] = 0.f;

    for (int k0 = 0; k0 < K; k0 += 8) {
        float4 av = *(const float4*)Ap;
        float4 wv = *(const float4*)Wp;
        Ap += 8; Wp += 8;
        As[lk + 0][lr] = av.x; As[lk + 1][lr] = av.y;
        As[lk + 2][lr] = av.z; As[lk + 3][lr] = av.w;
        Bs[lk + 0][lr] = wv.x; Bs[lk + 1][lr] = wv.y;
        Bs[lk + 2][lr] = wv.z; Bs[lk + 3][lr] = wv.w;
        __syncthreads();
#pragma unroll
        for (int kk = 0; kk < 8; kk++) {
            float a[8], b[8];
            *(float4*)&a[0] = *(const float4*)&As[kk][ty * 8];
            *(float4*)&a[4] = *(const float4*)&As[kk][ty * 8 + 4];
            *(float4*)&b[0] = *(const float4*)&Bs[kk][tx * 8];
            *(float4*)&b[4] = *(const float4*)&Bs[kk][tx * 8 + 4];
#pragma unroll
            for (int i = 0; i < 8; i++)
#pragma unroll
                for (int j = 0; j < 8; j++)
                    acc[i][j] += a[i] * b[j];
        }
        __syncthreads();
    }

    float bv[8];
#pragma unroll
    for (int j = 0; j < 8; j++) bv[j] = bias[n0 + tx * 8 + j];
#pragma unroll
    for (int i = 0; i < 8; i++) {
        float* Cp = C + (size_t)(m0 + ty * 8 + i) * N + n0 + tx * 8;
        float4 v0 = make_float4(acc[i][0] + bv[0], acc[i][1] + bv[1],
                                acc[i][2] + bv[2], acc[i][3] + bv[3]);
        float4 v1 = make_float4(acc[i][4] + bv[4], acc[i][5] + bv[5],
                                acc[i][6] + bv[6], acc[i][7] + bv[7]);
        *(float4*)Cp       = v0;
        *(float4*)(Cp + 4) = v1;
    }
}

// ---------------- fused GRU step ----------------
// Block computes hp[b, g, o] for a 32b x 32o tile, all 3 gates, then applies gates.
// grid = (H/32, B/32) = (32, 4); 256 threads; micro-tile 4b x (1o x 3g).
__global__ __launch_bounds__(256) void gru_step(
    const float* __restrict__ xp,      // [B*T, 3H], row m = b*T + t (bx already added)
    const float* __restrict__ Wh,      // [3H, H], row n = g*H + o
    const float* __restrict__ bh,      // [3H]
    const float* __restrict__ h_in,    // [B, H]
    float* __restrict__ h_out,         // [B, H]
    float* __restrict__ seq_out,       // [B*T, H]
    float* __restrict__ last_out,      // [B, H] or nullptr
    int t)
{
    __shared__ __align__(16) float Hs[16][32];   // [k][b]
    __shared__ __align__(16) float Ws[16][96];   // [k][o_local*3 + g]
    const int tid = threadIdx.x;
    const int o0 = blockIdx.x * 32;
    const int b0 = blockIdx.y * 32;
    const int tx = tid & 31;    // o_local
    const int ty = tid >> 5;    // b group (4 rows each)

    // H-tile loader: 8 threads per b-row, float2 along k
    const int hr = tid >> 3;
    const int hk = (tid & 7) << 1;
    const float* hload = h_in + (size_t)(b0 + hr) * H_ + hk;

    // W-tile loader: 96 rows x 16k = 768 float2, 3 per thread (indices hoisted)
    int wr[3], wk[3];
    const float* wload[3];
#pragma unroll
    for (int j = 0; j < 3; j++) {
        int lid = tid + j * 256;
        wr[j] = lid >> 3;                 // 0..95 = o_local*3 + g
        wk[j] = (lid & 7) << 1;
        int ol = wr[j] / 3;
        int g  = wr[j] - ol * 3;
        wload[j] = Wh + (size_t)(g * H_ + o0 + ol) * H_ + wk[j];
    }

    float acc[4][3];
#pragma unroll
    for (int i = 0; i < 4; i++) { acc[i][0] = 0.f; acc[i][1] = 0.f; acc[i][2] = 0.f; }

    for (int k0 = 0; k0 < H_; k0 += 16) {
        float2 hv = *(const float2*)(hload + k0);
        Hs[hk][hr]     = hv.x;
        Hs[hk + 1][hr] = hv.y;
#pragma unroll
        for (int j = 0; j < 3; j++) {
            float2 wv = *(const float2*)(wload[j] + k0);
            Ws[wk[j]][wr[j]]     = wv.x;
            Ws[wk[j] + 1][wr[j]] = wv.y;
        }
        __syncthreads();
#pragma unroll
        for (int kk = 0; kk < 16; kk++) {
            float a[4];
            *(float4*)a = *(const float4*)&Hs[kk][ty << 2];   // broadcast within warp
            float w0 = Ws[kk][tx * 3 + 0];                    // stride-3: conflict-free
            float w1 = Ws[kk][tx * 3 + 1];
            float w2 = Ws[kk][tx * 3 + 2];
#pragma unroll
            for (int i = 0; i < 4; i++) {
                acc[i][0] += a[i] * w0;
                acc[i][1] += a[i] * w1;
                acc[i][2] += a[i] * w2;
            }
        }
        __syncthreads();
    }

    // gate epilogue
    const int o = o0 + tx;
    const float bhr = bh[o];
    const float bhz = bh[H_ + o];
    const float bhn = bh[2 * H_ + o];
#pragma unroll
    for (int i = 0; i < 4; i++) {
        int b = b0 + (ty << 2) + i;
        size_t xrow = ((size_t)b * T_ + t) * (size_t)N3_;
        float xr = xp[xrow + o];
        float xz = xp[xrow + H_ + o];
        float xn = xp[xrow + 2 * H_ + o];
        float hprev = h_in[(size_t)b * H_ + o];
        float r  = 1.f / (1.f + expf(-(xr + acc[i][0] + bhr)));
        float z  = 1.f / (1.f + expf(-(xz + acc[i][1] + bhz)));
        float nn = tanhf(xn + r * (acc[i][2] + bhn));
        float hnew = (1.f - z) * nn + z * hprev;
        h_out[(size_t)b * H_ + o] = hnew;
        seq_out[((size_t)b * T_ + t) * (size_t)H_ + o] = hnew;
        if (last_out) last_out[(size_t)b * H_ + o] = hnew;
    }
}

// ---------------- launch ----------------
extern "C" void kernel_launch(void* const* d_in, const int* in_sizes, int n_in,
                              void* d_out, int out_size)
{
    const float* input       = (const float*)d_in[0];  // [B,T,H]
    const float* prev_hidden = (const float*)d_in[1];  // [L,B,H]
    const float* Wx          = (const float*)d_in[2];  // [L,3,H,H]
    const float* Wh          = (const float*)d_in[3];  // [L,3,H,H]
    const float* bx          = (const float*)d_in[4];  // [L,3,H]
    const float* bh          = (const float*)d_in[5];  // [L,3,H]
    float* out      = (float*)d_out;                   // [B,T,H] then [L,B,H]
    float* out_last = out + (size_t)B_ * T_ * H_;

    static float* p_xp  = nullptr;
    static float* p_seq = nullptr;
    static float* p_h   = nullptr;
    if (!p_xp) {
        cudaGetSymbolAddress((void**)&p_xp,  g_xp);
        cudaGetSymbolAddress((void**)&p_seq, g_seq1);
        cudaGetSymbolAddress((void**)&p_h,   g_hbuf);
    }

    dim3 gGrid(N3_ / 128, M_ / 128);   // (24, 128)
    dim3 sGrid(H_ / 32, B_ / 32);      // (32, 4) = 128 blocks

    for (int l = 0; l < L_; l++) {
        const float* Aseq = (l == 0) ? input : p_seq;
        sgemm_nt_bias<<<gGrid, 256>>>(Aseq,
                                      Wx + (size_t)l * 3 * H_ * H_,
                                      bx + (size_t)l * N3_,
                                      p_xp, M_, N3_, H_);
        float* seq_out = (l == 0) ? p_seq : out;
        for (int t = 0; t < T_; t++) {
            const float* h_in = (t == 0)
                ? (prev_hidden + (size_t)l * B_ * H_)
                : (p_h + (size_t)((t - 1) & 1) * B_ * H_);
            float* h_out = p_h + (size_t)(t & 1) * B_ * H_;
            float* last  = (t == T_ - 1) ? (out_last + (size_t)l * B_ * H_) : nullptr;
            gru_step<<<sGrid, 256>>>(p_xp,
                                     Wh + (size_t)l * 3 * H_ * H_,
                                     bh + (size_t)l * N3_,
                                     h_in, h_out, seq_out, last, t);
        }
    }
}

// round 6
// speedup vs baseline: 2.7366x; 2.7366x over previous
#include <cuda_runtime.h>
#include <cstdint>

#define Bb  128
#define Tt  128
#define Hh  1024
#define N3  3072
#define Mm  16384          // B*T

// ---------------- device scratch (static globals; no allocation) ----------------
__device__ __align__(128) float    g_xp[(size_t)Mm * N3];      // 201 MB
__device__ __align__(128) uint16_t g_Ahi[(size_t)Mm * Hh];     // 32 MB (layer input / layer-1 seq, hi)
__device__ __align__(128) uint16_t g_Alo[(size_t)Mm * Hh];     // 32 MB (lo)
__device__ __align__(128) uint16_t g_Wxhi[(size_t)N3 * Hh];
__device__ __align__(128) uint16_t g_Wxlo[(size_t)N3 * Hh];
__device__ __align__(128) uint16_t g_Whhi[(size_t)N3 * Hh];
__device__ __align__(128) uint16_t g_Whlo[(size_t)N3 * Hh];
__device__ __align__(128) float    g_h[2][Bb * Hh];
__device__ __align__(128) uint16_t g_hhi[2][Bb * Hh];
__device__ __align__(128) uint16_t g_hlo[2][Bb * Hh];

// ============================ helpers ============================
__device__ __forceinline__ uint32_t smem_u32(const void* p) {
    uint32_t a;
    asm("{ .reg .u64 t; cvta.to.shared.u64 t, %1; cvt.u32.u64 %0, t; }" : "=r"(a) : "l"(p));
    return a;
}
#define CPA(dst, src) asm volatile("cp.async.cg.shared.global [%0], [%1], 16;" :: "r"(dst), "l"(src))
#define CP_COMMIT()   asm volatile("cp.async.commit_group;" ::: "memory")

__device__ __forceinline__ void ldsm4(uint32_t* r, uint32_t addr) {
    asm volatile("ldmatrix.sync.aligned.m8n8.x4.shared.b16 {%0,%1,%2,%3}, [%4];"
        : "=r"(r[0]), "=r"(r[1]), "=r"(r[2]), "=r"(r[3]) : "r"(addr));
}
__device__ __forceinline__ void ldsm2(uint32_t* r, uint32_t addr) {
    asm volatile("ldmatrix.sync.aligned.m8n8.x2.shared.b16 {%0,%1}, [%2];"
        : "=r"(r[0]), "=r"(r[1]) : "r"(addr));
}
__device__ __forceinline__ void mma_bf16(float* c, const uint32_t* a, const uint32_t* b) {
    asm volatile(
        "mma.sync.aligned.m16n8k16.row.col.f32.bf16.bf16.f32 "
        "{%0,%1,%2,%3}, {%4,%5,%6,%7}, {%8,%9}, {%0,%1,%2,%3};"
        : "+f"(c[0]), "+f"(c[1]), "+f"(c[2]), "+f"(c[3])
        : "r"(a[0]), "r"(a[1]), "r"(a[2]), "r"(a[3]), "r"(b[0]), "r"(b[1]));
}

// hi/lo bf16 split of a pair of floats (packed b32: lower half = first elem)
__device__ __forceinline__ void split2(float a, float b, uint32_t& hi, uint32_t& lo) {
    asm("cvt.rn.bf16x2.f32 %0, %1, %2;" : "=r"(hi) : "f"(b), "f"(a));
    float ah = __uint_as_float(hi << 16);
    float bh = __uint_as_float(hi & 0xffff0000u);
    float ra = a - ah, rb = b - bh;
    asm("cvt.rn.bf16x2.f32 %0, %1, %2;" : "=r"(lo) : "f"(rb), "f"(ra));
}
__device__ __forceinline__ void split1(float x, uint16_t& h, uint16_t& l) {
    uint32_t p, q;
    asm("cvt.rn.bf16x2.f32 %0, %1, %1;" : "=r"(p) : "f"(x));
    h = (uint16_t)(p & 0xffffu);
    float hf = __uint_as_float(p << 16);
    float r = x - hf;
    asm("cvt.rn.bf16x2.f32 %0, %1, %1;" : "=r"(q) : "f"(r));
    l = (uint16_t)(q & 0xffffu);
}

// ---------------- fp32 -> (hi, lo) bf16 split, vectorized ----------------
__global__ void split_kernel(const float* __restrict__ src,
                             uint16_t* __restrict__ hi, uint16_t* __restrict__ lo, int n4) {
    int i = blockIdx.x * blockDim.x + threadIdx.x;
    if (i >= n4) return;
    float4 v = ((const float4*)src)[i];
    uint32_t h0, l0, h1, l1;
    split2(v.x, v.y, h0, l0);
    split2(v.z, v.w, h1, l1);
    ((uint2*)hi)[i] = make_uint2(h0, h1);
    ((uint2*)lo)[i] = make_uint2(l0, l1);
}

// ============ bulk GEMM (HMMA): C[m,n] = sum_k A[m,k]*W[n,k] + bias[n] ============
// 128x128 tile, k16 stages double-buffered, 8 warps (warp tile 64m x 32n), bf16x3 split.
__global__ __launch_bounds__(256, 1) void gemm_mma(
    const uint16_t* __restrict__ Ahi, const uint16_t* __restrict__ Alo,
    const uint16_t* __restrict__ Whi, const uint16_t* __restrict__ Wlo,
    const float* __restrict__ bias, float* __restrict__ C)
{
    __shared__ __align__(16) uint8_t sm[2][4][4096];   // [stage][Ahi,Alo,Whi,Wlo], 128 rows x 32B
    __shared__ float s_bias[128];
    const int tid = threadIdx.x, lane = tid & 31, wid = tid >> 5;
    const int m0 = blockIdx.y * 128, n0 = blockIdx.x * 128;
    const int wm = wid >> 2, wn = wid & 3;

    if (tid < 128) s_bias[tid] = bias[n0 + tid];

    // loader: thread -> (row, 16B-chunk)
    const int lrow = tid >> 1, lc = tid & 1;
    const uint32_t ld_off = (uint32_t)(lrow * 32 + ((lc ^ ((lrow >> 2) & 1)) * 16));
    const uint32_t sb = smem_u32(sm);
    const uint16_t* pAh = Ahi + (size_t)(m0 + lrow) * Hh + lc * 8;
    const uint16_t* pAl = Alo + (size_t)(m0 + lrow) * Hh + lc * 8;
    const uint16_t* pWh = Whi + (size_t)(n0 + lrow) * Hh + lc * 8;
    const uint16_t* pWl = Wlo + (size_t)(n0 + lrow) * Hh + lc * 8;

    // ldmatrix lane addresses (swizzle c ^= (row>>2)&1)
    const int arow = wm * 64 + (lane & 7) + ((lane >> 3) & 1) * 8;
    const int ac = lane >> 4;
    const uint32_t aOff = (uint32_t)(arow * 32 + ((ac ^ ((arow >> 2) & 1)) * 16));
    const int brow = wn * 32 + ((lane >> 4) & 1) * 8 + (lane & 7);
    const int bc = (lane >> 3) & 1;
    const uint32_t bOff = (uint32_t)(brow * 32 + ((bc ^ ((brow >> 2) & 1)) * 16));

    float acc[4][4][4];
#pragma unroll
    for (int mi = 0; mi < 4; mi++)
#pragma unroll
        for (int ni = 0; ni < 4; ni++)
#pragma unroll
            for (int j = 0; j < 4; j++) acc[mi][ni][j] = 0.f;

    auto issue = [&](int s) {
        uint32_t d = sb + (uint32_t)((s & 1) * 16384);
        int go = s * 16;
        CPA(d + 0 * 4096 + ld_off, pAh + go);
        CPA(d + 1 * 4096 + ld_off, pAl + go);
        CPA(d + 2 * 4096 + ld_off, pWh + go);
        CPA(d + 3 * 4096 + ld_off, pWl + go);
        CP_COMMIT();
    };
    issue(0);

    for (int s = 0; s < 64; s++) {
        if (s < 63) { issue(s + 1); asm volatile("cp.async.wait_group 1;" ::: "memory"); }
        else        { asm volatile("cp.async.wait_group 0;" ::: "memory"); }
        __syncthreads();
        const uint32_t st = sb + (uint32_t)((s & 1) * 16384);
        uint32_t ah[4][4], al[4][4], bh[4][2], bl[4][2];
#pragma unroll
        for (int mi = 0; mi < 4; mi++) {
            ldsm4(ah[mi], st + 0 * 4096 + aOff + mi * 512);
            ldsm4(al[mi], st + 1 * 4096 + aOff + mi * 512);
        }
#pragma unroll
        for (int p = 0; p < 2; p++) {
            uint32_t r[4];
            ldsm4(r, st + 2 * 4096 + bOff + p * 512);
            bh[2 * p][0] = r[0]; bh[2 * p][1] = r[1]; bh[2 * p + 1][0] = r[2]; bh[2 * p + 1][1] = r[3];
            ldsm4(r, st + 3 * 4096 + bOff + p * 512);
            bl[2 * p][0] = r[0]; bl[2 * p][1] = r[1]; bl[2 * p + 1][0] = r[2]; bl[2 * p + 1][1] = r[3];
        }
#pragma unroll
        for (int mi = 0; mi < 4; mi++)
#pragma unroll
            for (int ni = 0; ni < 4; ni++) {
                mma_bf16(acc[mi][ni], ah[mi], bh[ni]);   // hi*hi
                mma_bf16(acc[mi][ni], ah[mi], bl[ni]);   // hi*lo
                mma_bf16(acc[mi][ni], al[mi], bh[ni]);   // lo*hi
            }
        __syncthreads();
    }

    const int g = lane >> 2, tg2 = (lane & 3) * 2;
#pragma unroll
    for (int mi = 0; mi < 4; mi++) {
        const int mb = m0 + wm * 64 + mi * 16;
#pragma unroll
        for (int ni = 0; ni < 4; ni++) {
            const int nl = wn * 32 + ni * 8 + tg2;
            const float b0v = s_bias[nl], b1v = s_bias[nl + 1];
            float2 v0 = make_float2(acc[mi][ni][0] + b0v, acc[mi][ni][1] + b1v);
            float2 v1 = make_float2(acc[mi][ni][2] + b0v, acc[mi][ni][3] + b1v);
            *(float2*)&C[(size_t)(mb + g) * N3 + n0 + nl] = v0;
            *(float2*)&C[(size_t)(mb + g + 8) * N3 + n0 + nl] = v1;
        }
    }
}

// ============ GRU step (HMMA): hp = h @ Wh^T for 64b x (16o x 3 gates), then gates ============
// grid (H/16=64, B/64=2) = 128 blocks; 8 warps (warp tile 16m x 24n); k16 double-buffered.
__global__ __launch_bounds__(256, 1) void gru_mma(
    const float* __restrict__ xp,
    const uint16_t* __restrict__ Whhi, const uint16_t* __restrict__ Whlo,
    const float* __restrict__ bh,
    const float* __restrict__ h_f32_in,
    const uint16_t* __restrict__ h_hi_in, const uint16_t* __restrict__ h_lo_in,
    float* __restrict__ h_f32_out, uint16_t* __restrict__ h_hi_out, uint16_t* __restrict__ h_lo_out,
    float* __restrict__ seq_f32, uint16_t* __restrict__ seq_hi, uint16_t* __restrict__ seq_lo,
    float* __restrict__ last_out, int t)
{
    __shared__ __align__(16) uint8_t smA[2][2][2048];  // [stage][hi/lo] 64 rows x 32B
    __shared__ __align__(16) uint8_t smB[2][2][1536];  // [stage][hi/lo] 48 rows x 32B
    __shared__ float hp[48][69];                       // [n = g*16+o_l][b], pad 69
    const int tid = threadIdx.x, lane = tid & 31, wid = tid >> 5;
    const int o0 = blockIdx.x * 16, b0 = blockIdx.y * 64;
    const int wm = wid >> 1, wn = wid & 1;
    const uint32_t sA = smem_u32(smA), sB = smem_u32(smB);

    // A loader: 256 chunks (64 rows x 2 chunks x hi/lo), one per thread
    const int aHalf = tid >> 7, arw = (tid & 127) >> 1, acx = tid & 1;
    const uint32_t aDst = (uint32_t)(aHalf * 2048 + arw * 32 + ((acx ^ ((arw >> 2) & 1)) * 16));
    const uint16_t* aSrc = (aHalf ? h_lo_in : h_hi_in) + (size_t)(b0 + arw) * Hh + acx * 8;

    // B loader: 192 chunks (48 rows x 2 chunks x hi/lo), threads 0..191
    const bool bAct = tid < 192;
    const int u = tid < 96 ? tid : tid - 96;
    const int bHalf = tid >= 96 ? 1 : 0;
    const int brr = u >> 1, bcx = u & 1;
    const int bgx = brr >> 4, boo = brr & 15;          // Wh row = g*H + o0 + oo
    const uint32_t bDst = (uint32_t)(bHalf * 1536 + brr * 32 + ((bcx ^ ((brr >> 2) & 1)) * 16));
    const uint16_t* bSrc = (bHalf ? Whlo : Whhi) + (size_t)(bgx * Hh + o0 + boo) * Hh + bcx * 8;

    // ldmatrix lane addresses
    const int arow = wm * 16 + (lane & 7) + ((lane >> 3) & 1) * 8;
    const int ac2 = lane >> 4;
    const uint32_t aOff = (uint32_t)(arow * 32 + ((ac2 ^ ((arow >> 2) & 1)) * 16));
    const int brow = wn * 24 + ((lane >> 4) & 1) * 8 + (lane & 7);
    const int bc2 = (lane >> 3) & 1;
    const uint32_t bOff = (uint32_t)(brow * 32 + ((bc2 ^ ((brow >> 2) & 1)) * 16));
    const int brow2 = wn * 24 + 16 + (lane & 7);
    const uint32_t bOff2 = (uint32_t)(brow2 * 32 + ((bc2 ^ ((brow2 >> 2) & 1)) * 16));

    float acc[3][4];
#pragma unroll
    for (int ni = 0; ni < 3; ni++)
#pragma unroll
        for (int j = 0; j < 4; j++) acc[ni][j] = 0.f;

    auto issue = [&](int s) {
        uint32_t st = (uint32_t)(s & 1);
        CPA(sA + st * 4096 + aDst, aSrc + s * 16);
        if (bAct) CPA(sB + st * 3072 + bDst, bSrc + s * 16);
        CP_COMMIT();
    };
    issue(0);

    for (int s = 0; s < 64; s++) {
        if (s < 63) { issue(s + 1); asm volatile("cp.async.wait_group 1;" ::: "memory"); }
        else        { asm volatile("cp.async.wait_group 0;" ::: "memory"); }
        __syncthreads();
        const uint32_t stA = sA + (uint32_t)((s & 1) * 4096);
        const uint32_t stB = sB + (uint32_t)((s & 1) * 3072);
        uint32_t ah[4], al[4], bhf[3][2], blf[3][2], r[4];
        ldsm4(ah, stA + aOff);
        ldsm4(al, stA + 2048 + aOff);
        ldsm4(r, stB + bOff);
        bhf[0][0] = r[0]; bhf[0][1] = r[1]; bhf[1][0] = r[2]; bhf[1][1] = r[3];
        ldsm2(bhf[2], stB + bOff2);
        ldsm4(r, stB + 1536 + bOff);
        blf[0][0] = r[0]; blf[0][1] = r[1]; blf[1][0] = r[2]; blf[1][1] = r[3];
        ldsm2(blf[2], stB + 1536 + bOff2);
#pragma unroll
        for (int ni = 0; ni < 3; ni++) {
            mma_bf16(acc[ni], ah, bhf[ni]);
            mma_bf16(acc[ni], ah, blf[ni]);
            mma_bf16(acc[ni], al, bhf[ni]);
        }
        __syncthreads();
    }

    // stash hp to smem: hp[n][m]
    const int g = lane >> 2, tg2 = (lane & 3) * 2;
#pragma unroll
    for (int ni = 0; ni < 3; ni++) {
        const int nb = wn * 24 + ni * 8 + tg2;
        const int mb = wm * 16;
        hp[nb][mb + g]         = acc[ni][0];
        hp[nb + 1][mb + g]     = acc[ni][1];
        hp[nb][mb + g + 8]     = acc[ni][2];
        hp[nb + 1][mb + g + 8] = acc[ni][3];
    }
    __syncthreads();

    // gate phase: 16o x 64b, 4 b per thread
    const int o_l = tid & 15, bq = tid >> 4;
    const int o = o0 + o_l;
    const float bhr = bh[o], bhz = bh[Hh + o], bhn = bh[2 * Hh + o];
#pragma unroll
    for (int i = 0; i < 4; i++) {
        const int bl = bq * 4 + i;
        const int bg = b0 + bl;
        const float hr = hp[o_l][bl], hz = hp[16 + o_l][bl], hn = hp[32 + o_l][bl];
        const size_t xrow = ((size_t)bg * Tt + t) * N3;
        const float xr = xp[xrow + o], xz = xp[xrow + Hh + o], xn = xp[xrow + 2 * Hh + o];
        const float hprev = h_f32_in[(size_t)bg * Hh + o];
        const float rg = 1.f / (1.f + expf(-(xr + hr + bhr)));
        const float zg = 1.f / (1.f + expf(-(xz + hz + bhz)));
        const float ng = tanhf(xn + rg * (hn + bhn));
        const float hnew = (1.f - zg) * ng + zg * hprev;
        h_f32_out[(size_t)bg * Hh + o] = hnew;
        uint16_t hb, lb; split1(hnew, hb, lb);
        h_hi_out[(size_t)bg * Hh + o] = hb;
        h_lo_out[(size_t)bg * Hh + o] = lb;
        if (seq_hi) {
            const size_t sr = ((size_t)bg * Tt + t) * Hh + o;
            seq_hi[sr] = hb; seq_lo[sr] = lb;
        }
        if (seq_f32) seq_f32[((size_t)bg * Tt + t) * Hh + o] = hnew;
        if (last_out) last_out[(size_t)bg * Hh + o] = hnew;
    }
}

// ---------------- launch ----------------
extern "C" void kernel_launch(void* const* d_in, const int* in_sizes, int n_in,
                              void* d_out, int out_size)
{
    const float* input       = (const float*)d_in[0];  // [B,T,H]
    const float* prev_hidden = (const float*)d_in[1];  // [L,B,H]
    const float* Wx          = (const float*)d_in[2];  // [L,3,H,H]
    const float* Wh          = (const float*)d_in[3];  // [L,3,H,H]
    const float* bx          = (const float*)d_in[4];  // [L,3,H]
    const float* bh          = (const float*)d_in[5];  // [L,3,H]
    float* out      = (float*)d_out;                   // [B,T,H] then [L,B,H]
    float* out_last = out + (size_t)Bb * Tt * Hh;

    static float*    p_xp = nullptr;
    static uint16_t *p_Ahi, *p_Alo, *p_Wxhi, *p_Wxlo, *p_Whhi, *p_Whlo, *p_hhi, *p_hlo;
    static float*    p_h;
    if (!p_xp) {
        cudaGetSymbolAddress((void**)&p_xp,   g_xp);
        cudaGetSymbolAddress((void**)&p_Ahi,  g_Ahi);
        cudaGetSymbolAddress((void**)&p_Alo,  g_Alo);
        cudaGetSymbolAddress((void**)&p_Wxhi, g_Wxhi);
        cudaGetSymbolAddress((void**)&p_Wxlo, g_Wxlo);
        cudaGetSymbolAddress((void**)&p_Whhi, g_Whhi);
        cudaGetSymbolAddress((void**)&p_Whlo, g_Whlo);
        cudaGetSymbolAddress((void**)&p_h,    g_h);
        cudaGetSymbolAddress((void**)&p_hhi,  g_hhi);
        cudaGetSymbolAddress((void**)&p_hlo,  g_hlo);
    }

    const int BH = Bb * Hh;
    const dim3 gGrid(N3 / 128, Mm / 128);   // (24, 128)
    const dim3 sGrid(Hh / 16, Bb / 64);     // (64, 2)

    // split layer-1 input activations
    {
        int n4 = (Mm * Hh) / 4;
        split_kernel<<<(n4 + 255) / 256, 256>>>(input, p_Ahi, p_Alo, n4);
    }

    for (int l = 0; l < 2; l++) {
        const int nw4 = (N3 * Hh) / 4;
        split_kernel<<<(nw4 + 255) / 256, 256>>>(Wx + (size_t)l * N3 * Hh, p_Wxhi, p_Wxlo, nw4);
        gemm_mma<<<gGrid, 256>>>(p_Ahi, p_Alo, p_Wxhi, p_Wxlo, bx + (size_t)l * N3, p_xp);

        split_kernel<<<(nw4 + 255) / 256, 256>>>(Wh + (size_t)l * N3 * Hh, p_Whhi, p_Whlo, nw4);
        {
            int n4 = BH / 4;   // h0 split into slot 1 (read by t=0)
            split_kernel<<<(n4 + 255) / 256, 256>>>(prev_hidden + (size_t)l * BH,
                                                    p_hhi + 1 * BH, p_hlo + 1 * BH, n4);
        }

        for (int t = 0; t < Tt; t++) {
            const int rs = (t + 1) & 1, ws = t & 1;
            const float* h_in_f32 = (t == 0) ? (prev_hidden + (size_t)l * BH) : (p_h + (size_t)rs * BH);
            float*    seqf = (l == 1) ? out : nullptr;
            uint16_t* shi  = (l == 0) ? p_Ahi : nullptr;
            uint16_t* slo  = (l == 0) ? p_Alo : nullptr;
            float*    last = (t == Tt - 1) ? (out_last + (size_t)l * BH) : nullptr;
            gru_mma<<<sGrid, 256>>>(p_xp, p_Whhi, p_Whlo, bh + (size_t)l * N3,
                                    h_in_f32, p_hhi + (size_t)rs * BH, p_hlo + (size_t)rs * BH,
                                    p_h + (size_t)ws * BH, p_hhi + (size_t)ws * BH, p_hlo + (size_t)ws * BH,
                                    seqf, shi, slo, last, t);
        }
    }
}